// round 9
// baseline (speedup 1.0000x reference)
#include <cuda_runtime.h>

// Problem constants (shapes fixed by the dataset)
#define NMAX   100000
#define EMAX   3200000
#define F_INC  256
#define HIDC   16
#define CLSC   16
#define KST    2
#define JW     (KST*HIDC)   // 32 = K*HID fused stack width (layer1); also K*C (layer2)

// ---------------- device scratch (no allocations allowed) ----------------
__device__ int   g_is64;
__device__ float g_deg [NMAX];
__device__ float g_dinv[NMAX];
__device__ int   g_src [EMAX];
__device__ int   g_dst [EMAX];
__device__ float g_norm[EMAX];
__device__ float g_h1  [NMAX * JW];   // x @ init_w1  (both stacks)
__device__ float g_r1  [NMAX * JW];   // x @ root_w1
__device__ float g_agg1[NMAX * JW];
__device__ float g_h2  [NMAX * JW];   // h @ init_w2
__device__ float g_r2  [NMAX * JW];   // h @ root_w2
__device__ float g_agg2[NMAX * JW];

// ---------------- dtype detector: int64 vs int32 edge_index ----------------
// Values are node ids in [0, N). If stored as little-endian int64, every odd
// 32-bit word is 0. If int32, odd words are node ids (P(=0) = 1e-5 each).
__global__ void detect_kernel(const unsigned int* __restrict__ ei) {
    if (blockIdx.x == 0 && threadIdx.x == 0) {
        int nz = 0;
        for (int i = 1; i < 2048; i += 2) nz += (ei[i] != 0u);
        g_is64 = (nz == 0) ? 1 : 0;
    }
}

__device__ __forceinline__ int load_idx(const void* ei, long long i) {
    if (g_is64) return (int)((const long long*)ei)[i];
    return ((const int*)ei)[i];
}

// ---------------- zero scratch accumulators ----------------
__global__ void zero_kernel(int N) {
    int stride = gridDim.x * blockDim.x;
    int i0 = blockIdx.x * blockDim.x + threadIdx.x;
    for (int k = i0; k < N; k += stride) g_deg[k] = 0.f;
    int tot = N * JW;
    for (int k = i0; k < tot; k += stride) { g_agg1[k] = 0.f; g_agg2[k] = 0.f; }
}

// ---------------- degree (from dst / col index, matching gcn_norm) ----------------
__global__ void deg_kernel(const void* __restrict__ ei, int E) {
    int e = blockIdx.x * blockDim.x + threadIdx.x;
    if (e >= E) return;
    int d = load_idx(ei, (long long)E + e);
    atomicAdd(&g_deg[d], 1.0f);
}

__global__ void dinv_kernel(int N) {
    int n = blockIdx.x * blockDim.x + threadIdx.x;
    if (n >= N) return;
    float dg = g_deg[n];
    g_dinv[n] = (dg > 0.f) ? rsqrtf(dg) : 0.f;
}

// ---------------- edge prep: decode indices once, compute norm ----------------
__global__ void prep_kernel(const void* __restrict__ ei, int E) {
    int e = blockIdx.x * blockDim.x + threadIdx.x;
    if (e >= E) return;
    int s = load_idx(ei, e);
    int d = load_idx(ei, (long long)E + e);
    g_src[e] = s;
    g_dst[e] = d;
    g_norm[e] = g_dinv[s] * g_dinv[d];
}

// ---------------- GEMM1: h1 = x @ init_w1, r1 = x @ root_w1 (fused, 64 outs) ----
// Block: 256 threads, 64 nodes. Thread (nid = t/4, jq = t%4) computes 16 outputs.
__global__ __launch_bounds__(256) void gemm1_kernel(
    const float* __restrict__ x,
    const float* __restrict__ iw,   // [K, F_IN, HID]
    const float* __restrict__ rw,   // [K, F_IN, HID]
    int N)
{
    __shared__ float xs[64][65];    // padded: conflict-free
    __shared__ float ws[64][64];    // ws[fl][j]: j<32 init, j>=32 root

    int t   = threadIdx.x;
    int n0  = blockIdx.x * 64;
    int nid = t >> 2;
    int jq  = t & 3;
    int n   = n0 + nid;

    float acc[16];
    #pragma unroll
    for (int o = 0; o < 16; o++) acc[o] = 0.f;

    for (int f0 = 0; f0 < F_INC; f0 += 64) {
        // load x tile: 64 nodes x 64 features (coalesced float4)
        #pragma unroll
        for (int i = 0; i < 4; i++) {
            int idx = t + i * 256;          // 0..1023 float4 slots
            int nn  = idx >> 4;
            int fq  = idx & 15;
            float4 v = make_float4(0.f, 0.f, 0.f, 0.f);
            if (n0 + nn < N)
                v = *(const float4*)&x[(long long)(n0 + nn) * F_INC + f0 + fq * 4];
            xs[nn][fq * 4 + 0] = v.x;
            xs[nn][fq * 4 + 1] = v.y;
            xs[nn][fq * 4 + 2] = v.z;
            xs[nn][fq * 4 + 3] = v.w;
        }
        // load weight tile: 64 f x 64 j
        #pragma unroll
        for (int i = 0; i < 16; i++) {
            int idx = t + i * 256;          // 0..4095
            int fl  = idx >> 6;
            int j   = idx & 63;
            float v;
            if (j < 32)
                v = iw[(j >> 4) * (F_INC * HIDC) + (f0 + fl) * HIDC + (j & 15)];
            else {
                int jj = j - 32;
                v = rw[(jj >> 4) * (F_INC * HIDC) + (f0 + fl) * HIDC + (jj & 15)];
            }
            ws[fl][j] = v;
        }
        __syncthreads();

        #pragma unroll 8
        for (int fl = 0; fl < 64; fl++) {
            float xv = xs[nid][fl];
            const float4* w4 = (const float4*)&ws[fl][jq * 16];
            float4 w0 = w4[0], w1 = w4[1], w2 = w4[2], w3 = w4[3];
            acc[0]  = fmaf(xv, w0.x, acc[0]);
            acc[1]  = fmaf(xv, w0.y, acc[1]);
            acc[2]  = fmaf(xv, w0.z, acc[2]);
            acc[3]  = fmaf(xv, w0.w, acc[3]);
            acc[4]  = fmaf(xv, w1.x, acc[4]);
            acc[5]  = fmaf(xv, w1.y, acc[5]);
            acc[6]  = fmaf(xv, w1.z, acc[6]);
            acc[7]  = fmaf(xv, w1.w, acc[7]);
            acc[8]  = fmaf(xv, w2.x, acc[8]);
            acc[9]  = fmaf(xv, w2.y, acc[9]);
            acc[10] = fmaf(xv, w2.z, acc[10]);
            acc[11] = fmaf(xv, w2.w, acc[11]);
            acc[12] = fmaf(xv, w3.x, acc[12]);
            acc[13] = fmaf(xv, w3.y, acc[13]);
            acc[14] = fmaf(xv, w3.z, acc[14]);
            acc[15] = fmaf(xv, w3.w, acc[15]);
        }
        __syncthreads();
    }

    if (n < N) {
        float* base = (jq < 2) ? &g_h1[(long long)n * JW + jq * 16]
                               : &g_r1[(long long)n * JW + (jq - 2) * 16];
        float4* d4 = (float4*)base;
        d4[0] = make_float4(acc[0],  acc[1],  acc[2],  acc[3]);
        d4[1] = make_float4(acc[4],  acc[5],  acc[6],  acc[7]);
        d4[2] = make_float4(acc[8],  acc[9],  acc[10], acc[11]);
        d4[3] = make_float4(acc[12], acc[13], acc[14], acc[15]);
    }
}

// ---------------- edge scatter: agg[dst] += h[src] * norm (warp per edge) ------
#define EPW 4
__global__ __launch_bounds__(256) void scatter_kernel(int pass, int E) {
    const float* __restrict__ h = pass ? g_h2 : g_h1;
    float* agg = pass ? g_agg2 : g_agg1;
    int gid  = blockIdx.x * blockDim.x + threadIdx.x;
    int warp = gid >> 5;
    int lane = gid & 31;
    int e0 = warp * EPW;
    #pragma unroll
    for (int i = 0; i < EPW; i++) {
        int e = e0 + i;
        if (e < E) {
            int   s = g_src[e];
            int   d = g_dst[e];
            float w = g_norm[e];
            float v = h[(long long)s * JW + lane] * w;
            atomicAdd(&agg[(long long)d * JW + lane], v);
        }
    }
}

// ---------------- combine conv1 + GEMV into conv2 operands ----------------
// h = relu over stacks, mean over K; also emits agg_feature, g_h2, g_r2.
__global__ __launch_bounds__(256) void combine_kernel(
    const float* __restrict__ b1,    // [K, HID] = 32
    const float* __restrict__ iw2,   // [K, HID, C]
    const float* __restrict__ rw2,   // [K, HID, C]
    float* __restrict__ feat_out,    // may be null
    int N, int write_feat)
{
    __shared__ float w2s[16][64];    // w2s[o][j]: j<32 init, j>=32 root
    __shared__ float b1s[32];
    int t = threadIdx.x;
    for (int i = t; i < 1024; i += blockDim.x) {
        int o = i >> 6, j = i & 63;
        float v;
        if (j < 32)
            v = iw2[(j >> 4) * (HIDC * CLSC) + o * CLSC + (j & 15)];
        else {
            int jj = j - 32;
            v = rw2[(jj >> 4) * (HIDC * CLSC) + o * CLSC + (jj & 15)];
        }
        w2s[o][j] = v;
    }
    if (t < 32) b1s[t] = b1[t];
    __syncthreads();

    int n = blockIdx.x * blockDim.x + t;
    if (n >= N) return;

    float pre[32];
    const float4* a4 = (const float4*)&g_agg1[(long long)n * JW];
    const float4* r4 = (const float4*)&g_r1 [(long long)n * JW];
    #pragma unroll
    for (int q = 0; q < 8; q++) {
        float4 av = a4[q], rv = r4[q];
        pre[q * 4 + 0] = av.x + rv.x + b1s[q * 4 + 0];
        pre[q * 4 + 1] = av.y + rv.y + b1s[q * 4 + 1];
        pre[q * 4 + 2] = av.z + rv.z + b1s[q * 4 + 2];
        pre[q * 4 + 3] = av.w + rv.w + b1s[q * 4 + 3];
    }
    float h[16];
    #pragma unroll
    for (int o = 0; o < 16; o++) {
        float a0 = fmaxf(pre[o],      0.f);
        float a1 = fmaxf(pre[16 + o], 0.f);
        h[o] = 0.5f * (a0 + a1);   // mean over K; second relu is a no-op (>=0)
    }
    if (write_feat) {
        float4* f4 = (float4*)&feat_out[(long long)n * CLSC];
        f4[0] = make_float4(h[0],  h[1],  h[2],  h[3]);
        f4[1] = make_float4(h[4],  h[5],  h[6],  h[7]);
        f4[2] = make_float4(h[8],  h[9],  h[10], h[11]);
        f4[3] = make_float4(h[12], h[13], h[14], h[15]);
    }
    // conv2 GEMVs (weights broadcast from smem)
    float* h2 = &g_h2[(long long)n * JW];
    float* r2 = &g_r2[(long long)n * JW];
    #pragma unroll 4
    for (int j = 0; j < 32; j++) {
        float a = 0.f, b = 0.f;
        #pragma unroll
        for (int o = 0; o < 16; o++) {
            a = fmaf(h[o], w2s[o][j],      a);
            b = fmaf(h[o], w2s[o][j + 32], b);
        }
        h2[j] = a;
        r2[j] = b;
    }
}

// ---------------- final: combine conv2 + log_softmax ----------------
__global__ __launch_bounds__(256) void final_kernel(
    const float* __restrict__ b2, float* __restrict__ out, int N)
{
    __shared__ float b2s[32];
    if (threadIdx.x < 32) b2s[threadIdx.x] = b2[threadIdx.x];
    __syncthreads();

    int n = blockIdx.x * blockDim.x + threadIdx.x;
    if (n >= N) return;

    float pre[32];
    const float4* a4 = (const float4*)&g_agg2[(long long)n * JW];
    const float4* r4 = (const float4*)&g_r2 [(long long)n * JW];
    #pragma unroll
    for (int q = 0; q < 8; q++) {
        float4 av = a4[q], rv = r4[q];
        pre[q * 4 + 0] = av.x + rv.x + b2s[q * 4 + 0];
        pre[q * 4 + 1] = av.y + rv.y + b2s[q * 4 + 1];
        pre[q * 4 + 2] = av.z + rv.z + b2s[q * 4 + 2];
        pre[q * 4 + 3] = av.w + rv.w + b2s[q * 4 + 3];
    }
    float lg[16];
    float m = -1e30f;
    #pragma unroll
    for (int c = 0; c < 16; c++) {
        lg[c] = 0.5f * (pre[c] + pre[16 + c]);
        m = fmaxf(m, lg[c]);
    }
    float s = 0.f;
    #pragma unroll
    for (int c = 0; c < 16; c++) s += __expf(lg[c] - m);
    float lse = m + __logf(s);

    float4* o4 = (float4*)&out[(long long)n * CLSC];
    o4[0] = make_float4(lg[0] - lse,  lg[1] - lse,  lg[2] - lse,  lg[3] - lse);
    o4[1] = make_float4(lg[4] - lse,  lg[5] - lse,  lg[6] - lse,  lg[7] - lse);
    o4[2] = make_float4(lg[8] - lse,  lg[9] - lse,  lg[10] - lse, lg[11] - lse);
    o4[3] = make_float4(lg[12] - lse, lg[13] - lse, lg[14] - lse, lg[15] - lse);
}

// ---------------- launch ----------------
extern "C" void kernel_launch(void* const* d_in, const int* in_sizes, int n_in,
                              void* d_out, int out_size) {
    const float* x   = (const float*)d_in[0];
    const void*  ei  = d_in[1];                  // int32 or int64, detected on device
    const float* iw1 = (const float*)d_in[2];
    const float* rw1 = (const float*)d_in[3];
    const float* b1  = (const float*)d_in[4];
    const float* iw2 = (const float*)d_in[5];
    const float* rw2 = (const float*)d_in[6];
    const float* b2  = (const float*)d_in[7];
    float* out = (float*)d_out;

    int N = in_sizes[0] / F_INC;
    int E = in_sizes[1] / 2;
    if (N > NMAX) N = NMAX;
    if (E > EMAX) E = EMAX;

    int write_feat = (out_size >= 2 * N * CLSC) ? 1 : 0;
    float* feat_out = write_feat ? (out + (long long)N * CLSC) : out;

    detect_kernel<<<1, 32>>>((const unsigned int*)ei);
    zero_kernel<<<2048, 256>>>(N);
    deg_kernel<<<(E + 255) / 256, 256>>>(ei, E);
    dinv_kernel<<<(N + 255) / 256, 256>>>(N);
    prep_kernel<<<(E + 255) / 256, 256>>>(ei, E);
    gemm1_kernel<<<(N + 63) / 64, 256>>>(x, iw1, rw1, N);

    int edges_per_block = (256 / 32) * EPW;   // 32
    int sblocks = (E + edges_per_block - 1) / edges_per_block;
    scatter_kernel<<<sblocks, 256>>>(0, E);

    combine_kernel<<<(N + 255) / 256, 256>>>(b1, iw2, rw2, feat_out, N, write_feat);

    scatter_kernel<<<sblocks, 256>>>(1, E);

    final_kernel<<<(N + 255) / 256, 256>>>(b2, out, N);
}